// round 1
// baseline (speedup 1.0000x reference)
#include <cuda_runtime.h>
#include <math.h>

// Problem constants
constexpr int NN = 10000;    // nodes
constexpr int NE = 160000;   // edges
constexpr int C  = 256;      // channels
// H = 8 heads, D = 32 per head

// ---------------------------------------------------------------------------
// Scratch (device globals; no dynamic allocation allowed)
// ---------------------------------------------------------------------------
__device__ float g_x[NN * C];            // layernormed node feats
__device__ float g_vecs[NN * 3 * C];     // scaled vector feats
__device__ float g_q[NN * C];
__device__ float g_k[NN * C];
__device__ float g_v[NN * C];
__device__ float g_dk[(size_t)NE * C];
__device__ float g_dv[(size_t)NE * C];
__device__ float g_fact[(size_t)NE * C]; // silu(edge @ Wf + bf)
__device__ float g_pv[NN * 3 * 3 * C];   // vec @ Wvec  [N,3,768]
__device__ float g_vt[NN * 3 * C];       // vec @ Wtrg
__device__ float g_vs[NN * 3 * C];       // vec @ Wsrc
__device__ float g_vmsg[(size_t)NE * C];
__device__ float g_s[(size_t)NE * 2 * C];
__device__ float g_xagg[NN * C];
__device__ float g_vecout[NN * 3 * C];
__device__ float g_o[NN * 3 * C];        // x_agg @ Wo + bo

__device__ __forceinline__ float silu_f(float x) {
    return x / (1.0f + expf(-x));
}

// ---------------------------------------------------------------------------
// Zero the aggregation buffers (graph replays, so must zero every launch)
// ---------------------------------------------------------------------------
__global__ void zero_agg_kernel() {
    int idx = blockIdx.x * blockDim.x + threadIdx.x;
    int stride = gridDim.x * blockDim.x;
    for (int i = idx; i < NN * C; i += stride) g_xagg[i] = 0.0f;
    for (int i = idx; i < NN * 3 * C; i += stride) g_vecout[i] = 0.0f;
}

// ---------------------------------------------------------------------------
// LayerNorm over C=256, one block per node
// ---------------------------------------------------------------------------
__global__ void ln_kernel(const float* __restrict__ nf,
                          const float* __restrict__ sc,
                          const float* __restrict__ bi) {
    int n = blockIdx.x;
    int c = threadIdx.x;
    float v = nf[n * C + c];

    __shared__ float red[8];
    __shared__ float sh_mu, sh_rstd;

    float t = v;
    #pragma unroll
    for (int o = 16; o; o >>= 1) t += __shfl_xor_sync(0xffffffffu, t, o);
    if ((c & 31) == 0) red[c >> 5] = t;
    __syncthreads();
    if (c == 0) {
        float s = 0.f;
        #pragma unroll
        for (int i = 0; i < 8; i++) s += red[i];
        sh_mu = s * (1.0f / C);
    }
    __syncthreads();
    float mu = sh_mu;
    float d = v - mu;
    t = d * d;
    #pragma unroll
    for (int o = 16; o; o >>= 1) t += __shfl_xor_sync(0xffffffffu, t, o);
    __syncthreads();  // red reuse safety
    if ((c & 31) == 0) red[c >> 5] = t;
    __syncthreads();
    if (c == 0) {
        float s = 0.f;
        #pragma unroll
        for (int i = 0; i < 8; i++) s += red[i];
        sh_rstd = rsqrtf(s * (1.0f / C) + 1e-5f);
    }
    __syncthreads();
    g_x[n * C + c] = d * sh_rstd * sc[c] + bi[c];
}

// ---------------------------------------------------------------------------
// vecs = vector_feats * vln_w  (broadcast over last dim)
// ---------------------------------------------------------------------------
__global__ void vec_scale_kernel(const float* __restrict__ vf,
                                 const float* __restrict__ w) {
    int idx = blockIdx.x * blockDim.x + threadIdx.x;
    int stride = gridDim.x * blockDim.x;
    for (int i = idx; i < NN * 3 * C; i += stride)
        g_vecs[i] = vf[i] * w[i & (C - 1)];
}

// ---------------------------------------------------------------------------
// Generic SGEMM: Cmat[M,Ncols] = act(A[M,K] @ B[K,Ncols] + bias)
// 128x128 tile, BK=8, 256 threads, 8x8 per thread. Ncols % 128 == 0, K % 8 == 0.
// ACT: 0 = none, 1 = silu
// ---------------------------------------------------------------------------
template <int ACT>
__global__ void __launch_bounds__(256, 2)
sgemm_kernel(const float* __restrict__ A, const float* __restrict__ B,
             const float* __restrict__ bias, float* __restrict__ Cmat,
             int M, int Ncols, int K) {
    __shared__ float As[8][128];
    __shared__ float Bs[8][128];

    const int tid  = threadIdx.x;
    const int brow = blockIdx.y * 128;
    const int bcol = blockIdx.x * 128;

    const int aRow = tid >> 1;          // 0..127
    const int aCol = (tid & 1) << 2;    // 0 or 4
    const int bRow = tid >> 5;          // 0..7
    const int bCol = (tid & 31) << 2;   // 0..124

    const int ty = tid >> 4;            // 0..15
    const int tx = tid & 15;            // 0..15

    float acc[8][8];
    #pragma unroll
    for (int i = 0; i < 8; i++)
        #pragma unroll
        for (int j = 0; j < 8; j++) acc[i][j] = 0.f;

    const bool aValid = (brow + aRow) < M;
    const float* Arow = A + (size_t)(brow + aRow) * K;

    for (int k0 = 0; k0 < K; k0 += 8) {
        float4 a4 = make_float4(0.f, 0.f, 0.f, 0.f);
        if (aValid) a4 = *reinterpret_cast<const float4*>(Arow + k0 + aCol);
        As[aCol + 0][aRow] = a4.x;
        As[aCol + 1][aRow] = a4.y;
        As[aCol + 2][aRow] = a4.z;
        As[aCol + 3][aRow] = a4.w;
        *reinterpret_cast<float4*>(&Bs[bRow][bCol]) =
            *reinterpret_cast<const float4*>(B + (size_t)(k0 + bRow) * Ncols + bcol + bCol);
        __syncthreads();

        #pragma unroll
        for (int kk = 0; kk < 8; kk++) {
            float ra[8], rb[8];
            *reinterpret_cast<float4*>(ra)     = *reinterpret_cast<const float4*>(&As[kk][ty * 8]);
            *reinterpret_cast<float4*>(ra + 4) = *reinterpret_cast<const float4*>(&As[kk][ty * 8 + 4]);
            *reinterpret_cast<float4*>(rb)     = *reinterpret_cast<const float4*>(&Bs[kk][tx * 8]);
            *reinterpret_cast<float4*>(rb + 4) = *reinterpret_cast<const float4*>(&Bs[kk][tx * 8 + 4]);
            #pragma unroll
            for (int i = 0; i < 8; i++)
                #pragma unroll
                for (int j = 0; j < 8; j++)
                    acc[i][j] = fmaf(ra[i], rb[j], acc[i][j]);
        }
        __syncthreads();
    }

    #pragma unroll
    for (int i = 0; i < 8; i++) {
        int row = brow + ty * 8 + i;
        if (row >= M) continue;
        #pragma unroll
        for (int j = 0; j < 8; j += 4) {
            int col = bcol + tx * 8 + j;
            float4 r;
            float* pr = &r.x;
            #pragma unroll
            for (int u = 0; u < 4; u++) {
                float vb = bias ? bias[col + u] : 0.f;
                float vv = acc[i][j + u] + vb;
                if (ACT == 1) vv = vv / (1.f + expf(-vv));
                pr[u] = vv;
            }
            *reinterpret_cast<float4*>(&Cmat[(size_t)row * Ncols + col]) = r;
        }
    }
}

// ---------------------------------------------------------------------------
// Edge attention: attn = silu((q_i*k_j*dk).sum per head) * cutoff(dist)
// vmsg = v_j * dv * attn[head]
// One block (256 threads = 8 warps = 8 heads) per edge.
// ---------------------------------------------------------------------------
__global__ void edge_attn_kernel(const float* __restrict__ dist,
                                 const int* __restrict__ snd,
                                 const int* __restrict__ rcv) {
    int e = blockIdx.x;
    int c = threadIdx.x;
    int si = snd[e], ri = rcv[e];
    size_t eC = (size_t)e * C;

    float p = g_q[ri * C + c] * g_k[si * C + c] * g_dk[eC + c];
    #pragma unroll
    for (int o = 16; o; o >>= 1) p += __shfl_xor_sync(0xffffffffu, p, o);

    float a = silu_f(p);
    float dd = dist[e];
    float cut = (dd < 5.0f) ? 0.5f * (cosf(dd * 0.62831853071795865f) + 1.0f) : 0.0f;
    a *= cut;

    g_vmsg[eC + c] = g_v[si * C + c] * g_dv[eC + c] * a;
}

// ---------------------------------------------------------------------------
// Edge aggregation: scatter-add vmsg*mask and vec_msg*mask into node buffers
// ---------------------------------------------------------------------------
__global__ void edge_agg_kernel(const float* __restrict__ dij,
                                const float* __restrict__ mask,
                                const int* __restrict__ snd,
                                const int* __restrict__ rcv) {
    int e = blockIdx.x;
    int c = threadIdx.x;
    int si = snd[e], ri = rcv[e];
    float m = mask[e];
    size_t eC = (size_t)e * C;
    size_t e2C = (size_t)e * 2 * C;

    float vm = g_vmsg[eC + c] * m;
    float s1 = g_s[e2C + c];
    float s2 = g_s[e2C + C + c];
    float d0 = dij[e * 3 + 0], d1 = dij[e * 3 + 1], d2 = dij[e * 3 + 2];

    atomicAdd(&g_xagg[ri * C + c], vm);

    float msg0 = g_vecs[(si * 3 + 0) * C + c] * s1 + s2 * d0;
    float msg1 = g_vecs[(si * 3 + 1) * C + c] * s1 + s2 * d1;
    float msg2 = g_vecs[(si * 3 + 2) * C + c] * s1 + s2 * d2;
    atomicAdd(&g_vecout[(ri * 3 + 0) * C + c], msg0 * m);
    atomicAdd(&g_vecout[(ri * 3 + 1) * C + c], msg1 * m);
    atomicAdd(&g_vecout[(ri * 3 + 2) * C + c], msg2 * m);
}

// ---------------------------------------------------------------------------
// Finalize per-node outputs:
//   vec_dot = sum_a pv[:,a,0:256]*pv[:,a,256:512]
//   dx   = vec_dot * o2 + o3
//   dvec = pv[:,a,512:768] * o1 + vec_out
// ---------------------------------------------------------------------------
__global__ void finalize_kernel(float* __restrict__ out_dx,
                                float* __restrict__ out_dvec) {
    int n = blockIdx.x;
    int c = threadIdx.x;
    const float* pvn = g_pv + (size_t)n * 3 * 768;

    float vd = 0.f;
    #pragma unroll
    for (int a = 0; a < 3; a++)
        vd += pvn[a * 768 + c] * pvn[a * 768 + 256 + c];

    float o1 = g_o[n * 768 + c];
    float o2 = g_o[n * 768 + 256 + c];
    float o3 = g_o[n * 768 + 512 + c];

    out_dx[n * C + c] = vd * o2 + o3;
    #pragma unroll
    for (int a = 0; a < 3; a++)
        out_dvec[(n * 3 + a) * C + c] =
            pvn[a * 768 + 512 + c] * o1 + g_vecout[(n * 3 + a) * C + c];
}

// ---------------------------------------------------------------------------
// Edge update: df = silu(edge@Wf+bf) * w_dot * mask
// w1 = reject(vt[r], d), w2 = reject(vs[s], -d) == reject(vs[s], d)
// ---------------------------------------------------------------------------
__global__ void edge_update_kernel(const float* __restrict__ dij,
                                   const float* __restrict__ mask,
                                   const int* __restrict__ snd,
                                   const int* __restrict__ rcv,
                                   float* __restrict__ out_df) {
    int e = blockIdx.x;
    int c = threadIdx.x;
    int si = snd[e], ri = rcv[e];
    float d0 = dij[e * 3 + 0], d1 = dij[e * 3 + 1], d2 = dij[e * 3 + 2];

    float t0 = g_vt[(ri * 3 + 0) * C + c];
    float t1 = g_vt[(ri * 3 + 1) * C + c];
    float t2 = g_vt[(ri * 3 + 2) * C + c];
    float u0 = g_vs[(si * 3 + 0) * C + c];
    float u1 = g_vs[(si * 3 + 1) * C + c];
    float u2 = g_vs[(si * 3 + 2) * C + c];

    float p1 = t0 * d0 + t1 * d1 + t2 * d2;
    float p2 = u0 * d0 + u1 * d1 + u2 * d2;

    float w = (t0 - p1 * d0) * (u0 - p2 * d0)
            + (t1 - p1 * d1) * (u1 - p2 * d1)
            + (t2 - p1 * d2) * (u2 - p2 * d2);

    out_df[(size_t)e * C + c] = g_fact[(size_t)e * C + c] * w * mask[e];
}

// ---------------------------------------------------------------------------
// Launch
// ---------------------------------------------------------------------------
extern "C" void kernel_launch(void* const* d_in, const int* in_sizes, int n_in,
                              void* d_out, int out_size) {
    (void)in_sizes; (void)n_in; (void)out_size;

    const float* node_feats   = (const float*)d_in[0];
    const float* edge_feats   = (const float*)d_in[1];
    const float* vector_feats = (const float*)d_in[2];
    const float* distances    = (const float*)d_in[3];
    const float* d_ij         = (const float*)d_in[4];
    const float* mask         = (const float*)d_in[5];
    const int*   senders      = (const int*)d_in[6];
    const int*   receivers    = (const int*)d_in[7];
    const float* ln_scale     = (const float*)d_in[8];
    const float* ln_bias      = (const float*)d_in[9];
    const float* vln_w        = (const float*)d_in[10];
    const float* Wq  = (const float*)d_in[11];
    const float* bq  = (const float*)d_in[12];
    const float* Wk  = (const float*)d_in[13];
    const float* bk  = (const float*)d_in[14];
    const float* Wv  = (const float*)d_in[15];
    const float* bv  = (const float*)d_in[16];
    const float* Wdk = (const float*)d_in[17];
    const float* bdk = (const float*)d_in[18];
    const float* Wdv = (const float*)d_in[19];
    const float* bdv = (const float*)d_in[20];
    const float* Wvec = (const float*)d_in[21];
    const float* Ws  = (const float*)d_in[22];
    const float* bs  = (const float*)d_in[23];
    const float* Wo  = (const float*)d_in[24];
    const float* bo  = (const float*)d_in[25];
    const float* Wf  = (const float*)d_in[26];
    const float* bf  = (const float*)d_in[27];
    const float* Wsrc = (const float*)d_in[28];
    const float* Wtrg = (const float*)d_in[29];

    float* out      = (float*)d_out;
    float* out_dx   = out;
    float* out_df   = out + (size_t)NN * C;
    float* out_dvec = out + (size_t)NN * C + (size_t)NE * C;

    // Resolve scratch addresses (pure address query; graph-capture safe)
    float *p_x, *p_q, *p_k, *p_v, *p_dk, *p_dv, *p_fact, *p_vecs, *p_pv,
          *p_vt, *p_vs, *p_vmsg, *p_s, *p_xagg, *p_o;
    cudaGetSymbolAddress((void**)&p_x, g_x);
    cudaGetSymbolAddress((void**)&p_q, g_q);
    cudaGetSymbolAddress((void**)&p_k, g_k);
    cudaGetSymbolAddress((void**)&p_v, g_v);
    cudaGetSymbolAddress((void**)&p_dk, g_dk);
    cudaGetSymbolAddress((void**)&p_dv, g_dv);
    cudaGetSymbolAddress((void**)&p_fact, g_fact);
    cudaGetSymbolAddress((void**)&p_vecs, g_vecs);
    cudaGetSymbolAddress((void**)&p_pv, g_pv);
    cudaGetSymbolAddress((void**)&p_vt, g_vt);
    cudaGetSymbolAddress((void**)&p_vs, g_vs);
    cudaGetSymbolAddress((void**)&p_vmsg, g_vmsg);
    cudaGetSymbolAddress((void**)&p_s, g_s);
    cudaGetSymbolAddress((void**)&p_xagg, g_xagg);
    cudaGetSymbolAddress((void**)&p_o, g_o);

    auto grid_for = [](int M, int Ncols) {
        return dim3((unsigned)(Ncols / 128), (unsigned)((M + 127) / 128));
    };

    zero_agg_kernel<<<1024, 256>>>();
    ln_kernel<<<NN, 256>>>(node_feats, ln_scale, ln_bias);
    vec_scale_kernel<<<1024, 256>>>(vector_feats, vln_w);

    // Node-level GEMMs
    sgemm_kernel<0><<<grid_for(NN, C), 256>>>(p_x, Wq, bq, p_q, NN, C, C);
    sgemm_kernel<0><<<grid_for(NN, C), 256>>>(p_x, Wk, bk, p_k, NN, C, C);
    sgemm_kernel<0><<<grid_for(NN, C), 256>>>(p_x, Wv, bv, p_v, NN, C, C);
    sgemm_kernel<0><<<grid_for(NN * 3, 3 * C), 256>>>(p_vecs, Wvec, nullptr, p_pv, NN * 3, 3 * C, C);
    sgemm_kernel<0><<<grid_for(NN * 3, C), 256>>>(p_vecs, Wtrg, nullptr, p_vt, NN * 3, C, C);
    sgemm_kernel<0><<<grid_for(NN * 3, C), 256>>>(p_vecs, Wsrc, nullptr, p_vs, NN * 3, C, C);

    // Edge-level GEMMs
    sgemm_kernel<1><<<grid_for(NE, C), 256>>>(edge_feats, Wdk, bdk, p_dk, NE, C, C);
    sgemm_kernel<1><<<grid_for(NE, C), 256>>>(edge_feats, Wdv, bdv, p_dv, NE, C, C);
    sgemm_kernel<1><<<grid_for(NE, C), 256>>>(edge_feats, Wf, bf, p_fact, NE, C, C);

    // Edge attention -> vmsg
    edge_attn_kernel<<<NE, 256>>>(distances, senders, receivers);

    // s = silu(vmsg @ Ws + bs)
    sgemm_kernel<1><<<grid_for(NE, 2 * C), 256>>>(p_vmsg, Ws, bs, p_s, NE, 2 * C, C);

    // Aggregate to nodes
    edge_agg_kernel<<<NE, 256>>>(d_ij, mask, senders, receivers);

    // o = x_agg @ Wo + bo
    sgemm_kernel<0><<<grid_for(NN, 3 * C), 256>>>(p_xagg, Wo, bo, p_o, NN, 3 * C, C);

    // Node outputs
    finalize_kernel<<<NN, 256>>>(out_dx, out_dvec);

    // Edge outputs
    edge_update_kernel<<<NE, 256>>>(d_ij, mask, senders, receivers, out_df);
}

// round 3
// speedup vs baseline: 2.2036x; 2.2036x over previous
#include <cuda_runtime.h>
#include <math.h>
#include <stdint.h>

// Problem constants
constexpr int NN = 10000;    // nodes
constexpr int NE = 160000;   // edges
constexpr int C  = 256;      // channels (K of every GEMM)

// ---------------------------------------------------------------------------
// Scratch (device globals; no dynamic allocation allowed)
// ---------------------------------------------------------------------------
__device__ float g_x[NN * C];              // layernormed node feats
__device__ float g_vecs[NN * 3 * C];       // scaled vector feats
__device__ float g_qkv[NN * 768];          // [q | k | v]
__device__ float g_pvall[(size_t)NN * 3 * 1280];  // [pv(768) | vt(256) | vs(256)]
__device__ float g_edgecat[(size_t)NE * 768];     // [dk | dv | fact], all silu
__device__ float g_vmsg[(size_t)NE * C];
__device__ float g_s[(size_t)NE * 2 * C];
__device__ float g_xagg[NN * C];
__device__ float g_vecout[NN * 3 * C];
__device__ float g_o[NN * 3 * C];          // x_agg @ Wo + bo

// Packed weights
__device__ float g_Wqkv[C * 768];
__device__ float g_bqkv[768];
__device__ float g_Wvec3[C * 1280];
__device__ float g_Wedge[C * 768];
__device__ float g_bedge[768];

__device__ __forceinline__ float silu_f(float x) {
    return x / (1.0f + expf(-x));
}

// ---------------------------------------------------------------------------
// tf32 helpers
// ---------------------------------------------------------------------------
__device__ __forceinline__ uint32_t f2tf(float x) {
    uint32_t r;
    asm("cvt.rna.tf32.f32 %0, %1;" : "=r"(r) : "f"(x));
    return r;
}

__device__ __forceinline__ void cp16(uint32_t dst, const void* src, int sz) {
    asm volatile("cp.async.cg.shared.global [%0], [%1], 16, %2;\n"
                 :: "r"(dst), "l"(src), "r"(sz));
}
__device__ __forceinline__ void cp_commit() {
    asm volatile("cp.async.commit_group;\n");
}
template <int Nleft>
__device__ __forceinline__ void cp_wait() {
    asm volatile("cp.async.wait_group %0;\n" :: "n"(Nleft));
}

// ---------------------------------------------------------------------------
// Pack kernels (run each launch; deterministic)
// ---------------------------------------------------------------------------
__global__ void pack3_w(const float* __restrict__ W0, const float* __restrict__ W1,
                        const float* __restrict__ W2, float* __restrict__ dst) {
    // dst[k][768]: cols 0:256=W0, 256:512=W1, 512:768=W2 (each [256][256])
    int i = blockIdx.x * blockDim.x + threadIdx.x;
    if (i >= C * 768) return;
    int k = i / 768, j = i % 768;
    int part = j >> 8, jj = j & 255;
    const float* src = part == 0 ? W0 : (part == 1 ? W1 : W2);
    dst[i] = src[k * C + jj];
}

__global__ void pack3_b(const float* __restrict__ b0, const float* __restrict__ b1,
                        const float* __restrict__ b2, float* __restrict__ dst) {
    int j = threadIdx.x + blockIdx.x * blockDim.x;
    if (j >= 768) return;
    int part = j >> 8, jj = j & 255;
    const float* src = part == 0 ? b0 : (part == 1 ? b1 : b2);
    dst[j] = src[jj];
}

__global__ void pack_vec3(const float* __restrict__ Wvec, const float* __restrict__ Wtrg,
                          const float* __restrict__ Wsrc, float* __restrict__ dst) {
    // dst[k][1280]: 0:768=Wvec, 768:1024=Wtrg, 1024:1280=Wsrc
    int i = blockIdx.x * blockDim.x + threadIdx.x;
    if (i >= C * 1280) return;
    int k = i / 1280, j = i % 1280;
    float v;
    if (j < 768)       v = Wvec[k * 768 + j];
    else if (j < 1024) v = Wtrg[k * C + (j - 768)];
    else               v = Wsrc[k * C + (j - 1024)];
    dst[i] = v;
}

// ---------------------------------------------------------------------------
// Zero aggregation buffers (graph replays)
// ---------------------------------------------------------------------------
__global__ void zero_agg_kernel() {
    int idx = blockIdx.x * blockDim.x + threadIdx.x;
    int stride = gridDim.x * blockDim.x;
    for (int i = idx; i < NN * C; i += stride) g_xagg[i] = 0.0f;
    for (int i = idx; i < NN * 3 * C; i += stride) g_vecout[i] = 0.0f;
}

// ---------------------------------------------------------------------------
// LayerNorm over C=256, one block per node
// ---------------------------------------------------------------------------
__global__ void ln_kernel(const float* __restrict__ nf,
                          const float* __restrict__ sc,
                          const float* __restrict__ bi) {
    int n = blockIdx.x;
    int c = threadIdx.x;
    float v = nf[n * C + c];

    __shared__ float red[8];
    __shared__ float sh_mu, sh_rstd;

    float t = v;
    #pragma unroll
    for (int o = 16; o; o >>= 1) t += __shfl_xor_sync(0xffffffffu, t, o);
    if ((c & 31) == 0) red[c >> 5] = t;
    __syncthreads();
    if (c == 0) {
        float s = 0.f;
        #pragma unroll
        for (int i = 0; i < 8; i++) s += red[i];
        sh_mu = s * (1.0f / C);
    }
    __syncthreads();
    float mu = sh_mu;
    float d = v - mu;
    t = d * d;
    #pragma unroll
    for (int o = 16; o; o >>= 1) t += __shfl_xor_sync(0xffffffffu, t, o);
    __syncthreads();
    if ((c & 31) == 0) red[c >> 5] = t;
    __syncthreads();
    if (c == 0) {
        float s = 0.f;
        #pragma unroll
        for (int i = 0; i < 8; i++) s += red[i];
        sh_rstd = rsqrtf(s * (1.0f / C) + 1e-5f);
    }
    __syncthreads();
    g_x[n * C + c] = d * sh_rstd * sc[c] + bi[c];
}

__global__ void vec_scale_kernel(const float* __restrict__ vf,
                                 const float* __restrict__ w) {
    int idx = blockIdx.x * blockDim.x + threadIdx.x;
    int stride = gridDim.x * blockDim.x;
    for (int i = idx; i < NN * 3 * C; i += stride)
        g_vecs[i] = vf[i] * w[i & (C - 1)];
}

// ---------------------------------------------------------------------------
// TF32 tensor-core GEMM: Cmat[M,N] = act(A[M,256] @ B[256,N] + bias)
// 128x128 tile, BK=32, 256 threads = 8 warps (2x4), warp tile 64x32.
// mma.sync.aligned.m16n8k8.row.col.f32.tf32.tf32.f32.
// Double-buffered cp.async. N % 128 == 0. ACT: 0=none, 1=silu.
// ---------------------------------------------------------------------------
constexpr int AS_STRIDE = 36;    // floats per A row in smem (pad 32->36)
constexpr int BS_STRIDE = 136;   // floats per B row in smem (pad 128->136)
constexpr int AS_BUF = 128 * AS_STRIDE;  // 4608
constexpr int BS_BUF = 32 * BS_STRIDE;   // 4352
constexpr int SMEM_FLOATS = 2 * (AS_BUF + BS_BUF);  // 17920 -> 71680 B

template <int ACT>
__global__ void __launch_bounds__(256, 2)
mma_gemm(const float* __restrict__ A, const float* __restrict__ B,
         const float* __restrict__ bias, float* __restrict__ Cmat,
         int M, int N) {
    constexpr int K = 256;
    extern __shared__ float sm[];

    const int tid  = threadIdx.x;
    const int lane = tid & 31;
    const int wid  = tid >> 5;
    const int warp_m = wid >> 2;   // 0..1
    const int warp_n = wid & 3;    // 0..3

    const int brow = blockIdx.y * 128;
    const int bcol = blockIdx.x * 128;

    // Loader indices
    const int a_r  = tid >> 3;            // 0..31
    const int a_c4 = (tid & 7) << 2;      // 0..28
    const int b_k  = tid >> 5;            // 0..7
    const int b_n4 = (tid & 31) << 2;     // 0..124

    uint32_t sm_base;
    {
        uint32_t tmp;
        asm("{ .reg .u64 t; cvta.to.shared.u64 t, %1; cvt.u32.u64 %0, t; }"
            : "=r"(tmp) : "l"(sm));
        sm_base = tmp;
    }

    auto load_tile = [&](int k0, int buf) {
        uint32_t as_off = sm_base + (uint32_t)(buf * AS_BUF) * 4;
        uint32_t bs_off = sm_base + (uint32_t)(2 * AS_BUF + buf * BS_BUF) * 4;
        #pragma unroll
        for (int g = 0; g < 4; g++) {
            int r = a_r + g * 32;
            int row = brow + r;
            const float* src = A + (size_t)row * K + k0 + a_c4;
            cp16(as_off + (uint32_t)(r * AS_STRIDE + a_c4) * 4, src, row < M ? 16 : 0);
        }
        #pragma unroll
        for (int g = 0; g < 4; g++) {
            int kr = b_k + g * 8;
            const float* src = B + (size_t)(k0 + kr) * N + bcol + b_n4;
            cp16(bs_off + (uint32_t)(kr * BS_STRIDE + b_n4) * 4, src, 16);
        }
        cp_commit();
    };

    float acc[4][4][4];
    #pragma unroll
    for (int i = 0; i < 4; i++)
        #pragma unroll
        for (int j = 0; j < 4; j++)
            #pragma unroll
            for (int u = 0; u < 4; u++) acc[i][j][u] = 0.f;

    const int mrow = lane >> 2;   // 0..7
    const int kcol = lane & 3;    // 0..3
    const int bncol = lane >> 2;  // 0..7

    load_tile(0, 0);

    constexpr int TILES = K / 32;  // 8
    #pragma unroll 1
    for (int t = 0; t < TILES; t++) {
        if (t + 1 < TILES) {
            load_tile((t + 1) * 32, (t + 1) & 1);
            cp_wait<1>();
        } else {
            cp_wait<0>();
        }
        __syncthreads();

        const float* asb = sm + (t & 1) * AS_BUF;
        const float* bsb = sm + 2 * AS_BUF + (t & 1) * BS_BUF;

        #pragma unroll
        for (int kk = 0; kk < 4; kk++) {
            const int kb = kk * 8;
            uint32_t afr[4][4];
            #pragma unroll
            for (int mf = 0; mf < 4; mf++) {
                const float* p = asb + (warp_m * 64 + mf * 16 + mrow) * AS_STRIDE + kb + kcol;
                afr[mf][0] = f2tf(p[0]);
                afr[mf][1] = f2tf(p[8 * AS_STRIDE]);
                afr[mf][2] = f2tf(p[4]);
                afr[mf][3] = f2tf(p[8 * AS_STRIDE + 4]);
            }
            uint32_t bfr[4][2];
            #pragma unroll
            for (int nf = 0; nf < 4; nf++) {
                const float* q = bsb + (kb + kcol) * BS_STRIDE + warp_n * 32 + nf * 8 + bncol;
                bfr[nf][0] = f2tf(q[0]);
                bfr[nf][1] = f2tf(q[4 * BS_STRIDE]);
            }
            #pragma unroll
            for (int mf = 0; mf < 4; mf++)
                #pragma unroll
                for (int nf = 0; nf < 4; nf++) {
                    asm volatile(
                        "mma.sync.aligned.m16n8k8.row.col.f32.tf32.tf32.f32 "
                        "{%0,%1,%2,%3}, {%4,%5,%6,%7}, {%8,%9}, {%0,%1,%2,%3};\n"
                        : "+f"(acc[mf][nf][0]), "+f"(acc[mf][nf][1]),
                          "+f"(acc[mf][nf][2]), "+f"(acc[mf][nf][3])
                        : "r"(afr[mf][0]), "r"(afr[mf][1]), "r"(afr[mf][2]), "r"(afr[mf][3]),
                          "r"(bfr[nf][0]), "r"(bfr[nf][1]));
                }
        }
        __syncthreads();
    }

    // Epilogue: bias + act + store (float2 per c-pair)
    #pragma unroll
    for (int mf = 0; mf < 4; mf++) {
        int row0 = brow + warp_m * 64 + mf * 16 + mrow;
        #pragma unroll
        for (int nf = 0; nf < 4; nf++) {
            int col = bcol + warp_n * 32 + nf * 8 + (lane & 3) * 2;
            float b0 = bias ? bias[col] : 0.f;
            float b1 = bias ? bias[col + 1] : 0.f;
            float v0 = acc[mf][nf][0] + b0;
            float v1 = acc[mf][nf][1] + b1;
            float v2 = acc[mf][nf][2] + b0;
            float v3 = acc[mf][nf][3] + b1;
            if (ACT == 1) {
                v0 = silu_f(v0); v1 = silu_f(v1);
                v2 = silu_f(v2); v3 = silu_f(v3);
            }
            if (row0 < M)
                *reinterpret_cast<float2*>(&Cmat[(size_t)row0 * N + col]) = make_float2(v0, v1);
            if (row0 + 8 < M)
                *reinterpret_cast<float2*>(&Cmat[(size_t)(row0 + 8) * N + col]) = make_float2(v2, v3);
        }
    }
}

// ---------------------------------------------------------------------------
// Edge attention: attn = silu((q_i*k_j*dk).sum per head) * cutoff(dist)
// vmsg = v_j * dv * attn[head]; one block (8 warps = 8 heads) per edge.
// ---------------------------------------------------------------------------
__global__ void edge_attn_kernel(const float* __restrict__ dist,
                                 const int* __restrict__ snd,
                                 const int* __restrict__ rcv) {
    int e = blockIdx.x;
    int c = threadIdx.x;
    int si = snd[e], ri = rcv[e];
    size_t e768 = (size_t)e * 768;

    float qv = g_qkv[ri * 768 + c];
    float kv = g_qkv[si * 768 + 256 + c];
    float p = qv * kv * g_edgecat[e768 + c];
    #pragma unroll
    for (int o = 16; o; o >>= 1) p += __shfl_xor_sync(0xffffffffu, p, o);

    float a = silu_f(p);
    float dd = dist[e];
    float cut = (dd < 5.0f) ? 0.5f * (cosf(dd * 0.62831853071795865f) + 1.0f) : 0.0f;
    a *= cut;

    g_vmsg[(size_t)e * C + c] = g_qkv[si * 768 + 512 + c] * g_edgecat[e768 + 256 + c] * a;
}

// ---------------------------------------------------------------------------
// Edge aggregation
// ---------------------------------------------------------------------------
__global__ void edge_agg_kernel(const float* __restrict__ dij,
                                const float* __restrict__ mask,
                                const int* __restrict__ snd,
                                const int* __restrict__ rcv) {
    int e = blockIdx.x;
    int c = threadIdx.x;
    int si = snd[e], ri = rcv[e];
    float m = mask[e];
    size_t eC = (size_t)e * C;
    size_t e2C = (size_t)e * 2 * C;

    float vm = g_vmsg[eC + c] * m;
    float s1 = g_s[e2C + c];
    float s2 = g_s[e2C + C + c];
    float d0 = dij[e * 3 + 0], d1 = dij[e * 3 + 1], d2 = dij[e * 3 + 2];

    atomicAdd(&g_xagg[ri * C + c], vm);

    float msg0 = g_vecs[(si * 3 + 0) * C + c] * s1 + s2 * d0;
    float msg1 = g_vecs[(si * 3 + 1) * C + c] * s1 + s2 * d1;
    float msg2 = g_vecs[(si * 3 + 2) * C + c] * s1 + s2 * d2;
    atomicAdd(&g_vecout[(ri * 3 + 0) * C + c], msg0 * m);
    atomicAdd(&g_vecout[(ri * 3 + 1) * C + c], msg1 * m);
    atomicAdd(&g_vecout[(ri * 3 + 2) * C + c], msg2 * m);
}

// ---------------------------------------------------------------------------
// Finalize per-node outputs
// ---------------------------------------------------------------------------
__global__ void finalize_kernel(float* __restrict__ out_dx,
                                float* __restrict__ out_dvec) {
    int n = blockIdx.x;
    int c = threadIdx.x;
    const float* pvn = g_pvall + (size_t)n * 3 * 1280;

    float vd = 0.f;
    #pragma unroll
    for (int a = 0; a < 3; a++)
        vd += pvn[a * 1280 + c] * pvn[a * 1280 + 256 + c];

    float o1 = g_o[n * 768 + c];
    float o2 = g_o[n * 768 + 256 + c];
    float o3 = g_o[n * 768 + 512 + c];

    out_dx[n * C + c] = vd * o2 + o3;
    #pragma unroll
    for (int a = 0; a < 3; a++)
        out_dvec[(n * 3 + a) * C + c] =
            pvn[a * 1280 + 512 + c] * o1 + g_vecout[(n * 3 + a) * C + c];
}

// ---------------------------------------------------------------------------
// Edge update
// ---------------------------------------------------------------------------
__global__ void edge_update_kernel(const float* __restrict__ dij,
                                   const float* __restrict__ mask,
                                   const int* __restrict__ snd,
                                   const int* __restrict__ rcv,
                                   float* __restrict__ out_df) {
    int e = blockIdx.x;
    int c = threadIdx.x;
    int si = snd[e], ri = rcv[e];
    float d0 = dij[e * 3 + 0], d1 = dij[e * 3 + 1], d2 = dij[e * 3 + 2];

    float t0 = g_pvall[((size_t)ri * 3 + 0) * 1280 + 768 + c];
    float t1 = g_pvall[((size_t)ri * 3 + 1) * 1280 + 768 + c];
    float t2 = g_pvall[((size_t)ri * 3 + 2) * 1280 + 768 + c];
    float u0 = g_pvall[((size_t)si * 3 + 0) * 1280 + 1024 + c];
    float u1 = g_pvall[((size_t)si * 3 + 1) * 1280 + 1024 + c];
    float u2 = g_pvall[((size_t)si * 3 + 2) * 1280 + 1024 + c];

    float p1 = t0 * d0 + t1 * d1 + t2 * d2;
    float p2 = u0 * d0 + u1 * d1 + u2 * d2;

    float w = (t0 - p1 * d0) * (u0 - p2 * d0)
            + (t1 - p1 * d1) * (u1 - p2 * d1)
            + (t2 - p1 * d2) * (u2 - p2 * d2);

    out_df[(size_t)e * C + c] = g_edgecat[(size_t)e * 768 + 512 + c] * w * mask[e];
}

// ---------------------------------------------------------------------------
// Launch
// ---------------------------------------------------------------------------
extern "C" void kernel_launch(void* const* d_in, const int* in_sizes, int n_in,
                              void* d_out, int out_size) {
    (void)in_sizes; (void)n_in; (void)out_size;

    const float* node_feats   = (const float*)d_in[0];
    const float* edge_feats   = (const float*)d_in[1];
    const float* vector_feats = (const float*)d_in[2];
    const float* distances    = (const float*)d_in[3];
    const float* d_ij         = (const float*)d_in[4];
    const float* mask         = (const float*)d_in[5];
    const int*   senders      = (const int*)d_in[6];
    const int*   receivers    = (const int*)d_in[7];
    const float* ln_scale     = (const float*)d_in[8];
    const float* ln_bias      = (const float*)d_in[9];
    const float* vln_w        = (const float*)d_in[10];
    const float* Wq  = (const float*)d_in[11];
    const float* bq  = (const float*)d_in[12];
    const float* Wk  = (const float*)d_in[13];
    const float* bk  = (const float*)d_in[14];
    const float* Wv  = (const float*)d_in[15];
    const float* bv  = (const float*)d_in[16];
    const float* Wdk = (const float*)d_in[17];
    const float* bdk = (const float*)d_in[18];
    const float* Wdv = (const float*)d_in[19];
    const float* bdv = (const float*)d_in[20];
    const float* Wvec = (const float*)d_in[21];
    const float* Ws  = (const float*)d_in[22];
    const float* bs  = (const float*)d_in[23];
    const float* Wo  = (const float*)d_in[24];
    const float* bo  = (const float*)d_in[25];
    const float* Wf  = (const float*)d_in[26];
    const float* bf  = (const float*)d_in[27];
    const float* Wsrc = (const float*)d_in[28];
    const float* Wtrg = (const float*)d_in[29];

    float* out      = (float*)d_out;
    float* out_dx   = out;
    float* out_df   = out + (size_t)NN * C;
    float* out_dvec = out + (size_t)NN * C + (size_t)NE * C;

    float *p_x, *p_vecs, *p_qkv, *p_pvall, *p_edgecat, *p_vmsg, *p_s, *p_xagg, *p_o;
    float *p_Wqkv, *p_bqkv, *p_Wvec3, *p_Wedge, *p_bedge;
    cudaGetSymbolAddress((void**)&p_x, g_x);
    cudaGetSymbolAddress((void**)&p_vecs, g_vecs);
    cudaGetSymbolAddress((void**)&p_qkv, g_qkv);
    cudaGetSymbolAddress((void**)&p_pvall, g_pvall);
    cudaGetSymbolAddress((void**)&p_edgecat, g_edgecat);
    cudaGetSymbolAddress((void**)&p_vmsg, g_vmsg);
    cudaGetSymbolAddress((void**)&p_s, g_s);
    cudaGetSymbolAddress((void**)&p_xagg, g_xagg);
    cudaGetSymbolAddress((void**)&p_o, g_o);
    cudaGetSymbolAddress((void**)&p_Wqkv, g_Wqkv);
    cudaGetSymbolAddress((void**)&p_bqkv, g_bqkv);
    cudaGetSymbolAddress((void**)&p_Wvec3, g_Wvec3);
    cudaGetSymbolAddress((void**)&p_Wedge, g_Wedge);
    cudaGetSymbolAddress((void**)&p_bedge, g_bedge);

    const size_t smem_bytes = (size_t)SMEM_FLOATS * 4;  // 71680
    cudaFuncSetAttribute(mma_gemm<0>, cudaFuncAttributeMaxDynamicSharedMemorySize,
                         (int)smem_bytes);
    cudaFuncSetAttribute(mma_gemm<1>, cudaFuncAttributeMaxDynamicSharedMemorySize,
                         (int)smem_bytes);

    auto grid_for = [](int M, int Ncols) {
        return dim3((unsigned)(Ncols / 128), (unsigned)((M + 127) / 128));
    };

    // Pack weights
    pack3_w<<<(C * 768 + 255) / 256, 256>>>(Wq, Wk, Wv, p_Wqkv);
    pack3_b<<<3, 256>>>(bq, bk, bv, p_bqkv);
    pack_vec3<<<(C * 1280 + 255) / 256, 256>>>(Wvec, Wtrg, Wsrc, p_Wvec3);
    pack3_w<<<(C * 768 + 255) / 256, 256>>>(Wdk, Wdv, Wf, p_Wedge);
    pack3_b<<<3, 256>>>(bdk, bdv, bf, p_bedge);

    zero_agg_kernel<<<1024, 256>>>();
    ln_kernel<<<NN, 256>>>(node_feats, ln_scale, ln_bias);
    vec_scale_kernel<<<1024, 256>>>(vector_feats, vln_w);

    // GEMMs (all K=256)
    mma_gemm<0><<<grid_for(NN, 768), 256, smem_bytes>>>(p_x, p_Wqkv, p_bqkv, p_qkv, NN, 768);
    mma_gemm<0><<<grid_for(NN * 3, 1280), 256, smem_bytes>>>(p_vecs, p_Wvec3, nullptr, p_pvall, NN * 3, 1280);
    mma_gemm<1><<<grid_for(NE, 768), 256, smem_bytes>>>(edge_feats, p_Wedge, p_bedge, p_edgecat, NE, 768);

    edge_attn_kernel<<<NE, 256>>>(distances, senders, receivers);

    mma_gemm<1><<<grid_for(NE, 512), 256, smem_bytes>>>(p_vmsg, Ws, bs, p_s, NE, 512);

    edge_agg_kernel<<<NE, 256>>>(d_ij, mask, senders, receivers);

    mma_gemm<0><<<grid_for(NN, 768), 256, smem_bytes>>>(p_xagg, Wo, bo, p_o, NN, 768);

    finalize_kernel<<<NN, 256>>>(out_dx, out_dvec);
    edge_update_kernel<<<NE, 256>>>(d_ij, mask, senders, receivers, out_df);
}